// round 15
// baseline (speedup 1.0000x reference)
#include <cuda_runtime.h>
#include <cuda_fp16.h>
#include <cstdint>
#include <math.h>

#define TOK 50176            // 16 * 56 * 56 tokens

// ---------------- scratch (device globals; no allocation allowed) ----------
__device__ __half g_xn [TOK * 384];    // LN output (fp16)
__device__ __half g_qkv[TOK * 1152];   // QKV activations (fp16)
__device__ __half g_o  [TOK * 384];    // attention output (fp16)
__device__ __half g_h1 [TOK * 1536];   // MLP hidden (fp16)
__device__ __half g_wt [2 * 1769472];  // transposed fp16 weights [N,K] per block

// ---------------- helpers ----------------------------------------------------
__device__ __forceinline__ void cp16s(uint32_t saddr, const void* g)
{
    asm volatile("cp.async.cg.shared.global [%0], [%1], 16;\n" :: "r"(saddr), "l"(g));
}
__device__ __forceinline__ uint32_t smem_u32(const void* p)
{
    uint32_t a;
    asm("{ .reg .u64 t; cvta.to.shared.u64 t, %1; cvt.u32.u64 %0, t; }" : "=r"(a) : "l"(p));
    return a;
}
#define LDSM4(r0, r1, r2, r3, addr) \
    asm volatile("ldmatrix.sync.aligned.m8n8.x4.shared.b16 {%0,%1,%2,%3}, [%4];" \
                 : "=r"(r0), "=r"(r1), "=r"(r2), "=r"(r3) : "r"(addr))
#define MMA16816(d, a0, a1, a2, a3, b0, b1) \
    asm volatile("mma.sync.aligned.m16n8k16.row.col.f32.f16.f16.f32 " \
                 "{%0,%1,%2,%3}, {%4,%5,%6,%7}, {%8,%9}, {%0,%1,%2,%3};\n" \
                 : "+f"((d)[0]), "+f"((d)[1]), "+f"((d)[2]), "+f"((d)[3]) \
                 : "r"(a0), "r"(a1), "r"(a2), "r"(a3), "r"(b0), "r"(b1))

// ---------------- fp16 tensor-core GEMM: BM=BN=128, warp tile 32x64 ---------
// 256 threads (4 warps M x 2 warps N), 3-stage cp.async, ONE barrier/iter.
// C[M,N] = A[M,K] @ Bt[N,K]^T + bias   (A,Bt fp16; accumulate fp32)
// MODE 0: store fp16   MODE 1: gelu -> fp16   MODE 2: fp32 residual add
#define BK 64
#define PITCH 72
#define STG_A (128 * PITCH * 2)        // 18432 B per operand per stage
#define STAGE (2 * STG_A)
#define SM_BIAS (3 * STAGE)
#define GEMM_SMEM (3 * STAGE + 512)    // 111104 B -> 2 CTAs/SM

template<int MODE, typename TOut>
__global__ __launch_bounds__(256, 2)
void gemm_fp16(const __half* __restrict__ A, const __half* __restrict__ Bt,
               const float* __restrict__ bias, TOut* __restrict__ Cout,
               int N, int K)
{
    extern __shared__ __align__(1024) char smem[];
    uint32_t sb = smem_u32(smem);
    float* bias_s = (float*)(smem + SM_BIAS);

    int tid  = threadIdx.x;
    int bn   = blockIdx.x, bm = blockIdx.y;
    int warp = tid >> 5, lane = tid & 31;
    int wm   = warp & 3;            // 4 warps along M (32 rows each)
    int wn   = warp >> 2;           // 2 warps along N (64 cols each)
    int g    = lane >> 2, t = lane & 3;
    int sub  = lane >> 3, r = lane & 7;

    if (tid < 128) bias_s[tid] = bias[bn * 128 + tid];

    float acc[2][8][4];
#pragma unroll
    for (int i = 0; i < 2; i++)
#pragma unroll
        for (int j = 0; j < 8; j++)
#pragma unroll
            for (int k = 0; k < 4; k++) acc[i][j][k] = 0.f;

    const __half* Ag = A  + (size_t)bm * 128 * K;
    const __half* Bg = Bt + (size_t)bn * 128 * K;

    // A,B: 128 rows x 8 chunks(16B) = 1024 each -> 4/thread each
    int ldrow = tid >> 1;                // 0..127
    int ldc0  = (tid & 1) * 4;           // 0 or 4

    uint32_t aoff = (uint32_t)(((wm * 32 + (lane & 15)) * PITCH + (lane >> 4) * 8) * 2);
    uint32_t boff = (uint32_t)(((wn * 64 + (sub >> 1) * 8 + r) * PITCH + (sub & 1) * 8) * 2);

    auto load_stage = [&](int stg, int kc) {
        uint32_t base = sb + (uint32_t)(stg * STAGE);
        int k0 = kc * BK;
#pragma unroll
        for (int c = 0; c < 4; c++) {
            uint32_t so = (uint32_t)(ldrow * PITCH + (ldc0 + c) * 8) * 2;
            cp16s(base + so,         Ag + (size_t)ldrow * K + k0 + (ldc0 + c) * 8);
            cp16s(base + STG_A + so, Bg + (size_t)ldrow * K + k0 + (ldc0 + c) * 8);
        }
    };

    int NK = K / BK;
    load_stage(0, 0);
    asm volatile("cp.async.commit_group;");
    load_stage(1, 1);
    asm volatile("cp.async.commit_group;");

    for (int kc = 0; kc < NK; kc++) {
        int buf = kc % 3;
        if (kc + 1 < NK) asm volatile("cp.async.wait_group 1;");
        else             asm volatile("cp.async.wait_group 0;");
        __syncthreads();
        if (kc + 2 < NK) {
            load_stage((kc + 2) % 3, kc + 2);
            asm volatile("cp.async.commit_group;");
        }

        uint32_t abase = sb + (uint32_t)(buf * STAGE) + aoff;
        uint32_t bbase = sb + (uint32_t)(buf * STAGE) + STG_A + boff;
#pragma unroll
        for (int ks = 0; ks < 4; ks++) {
            uint32_t a[2][4];
#pragma unroll
            for (int mt = 0; mt < 2; mt++)
                LDSM4(a[mt][0], a[mt][1], a[mt][2], a[mt][3],
                      abase + mt * (16 * PITCH * 2) + ks * 32);
            uint32_t b[4][4];
#pragma unroll
            for (int np = 0; np < 4; np++)
                LDSM4(b[np][0], b[np][1], b[np][2], b[np][3],
                      bbase + np * (16 * PITCH * 2) + ks * 32);
#pragma unroll
            for (int mt = 0; mt < 2; mt++)
#pragma unroll
                for (int nt = 0; nt < 8; nt++)
                    MMA16816(acc[mt][nt], a[mt][0], a[mt][1], a[mt][2], a[mt][3],
                             b[nt >> 1][(nt & 1) * 2], b[nt >> 1][(nt & 1) * 2 + 1]);
        }
    }

#pragma unroll
    for (int mt = 0; mt < 2; mt++) {
#pragma unroll
        for (int nt = 0; nt < 8; nt++) {
            int row = bm * 128 + wm * 32 + mt * 16 + g;
            int cl  = wn * 64 + nt * 8 + t * 2;
            int col = bn * 128 + cl;
            float b0 = bias_s[cl], b1 = bias_s[cl + 1];
            float v00 = acc[mt][nt][0] + b0, v01 = acc[mt][nt][1] + b1;
            float v10 = acc[mt][nt][2] + b0, v11 = acc[mt][nt][3] + b1;
            if (MODE == 1) {
                v00 = 0.5f * v00 * (1.f + erff(v00 * 0.70710678118654752f));
                v01 = 0.5f * v01 * (1.f + erff(v01 * 0.70710678118654752f));
                v10 = 0.5f * v10 * (1.f + erff(v10 * 0.70710678118654752f));
                v11 = 0.5f * v11 * (1.f + erff(v11 * 0.70710678118654752f));
            }
            size_t i0 = (size_t)row * N + col;
            size_t i1 = (size_t)(row + 8) * N + col;
            if (MODE == 2) {
                float* C = (float*)Cout;
                C[i0] += v00; C[i0 + 1] += v01;
                C[i1] += v10; C[i1 + 1] += v11;
            } else {
                __half* C = (__half*)Cout;
                *(__half2*)(C + i0) = __floats2half2_rn(v00, v01);
                *(__half2*)(C + i1) = __floats2half2_rn(v10, v11);
            }
        }
    }
}

// ---------------- fused weight transpose+convert (one launch per block i) --
__global__ __launch_bounds__(256)
void transpose_all(const float* __restrict__ qkvw, const float* __restrict__ projw,
                   const float* __restrict__ fc1w, const float* __restrict__ fc2w,
                   __half* __restrict__ wt, int i)
{
    __shared__ float tbuf[32][33];
    int rem = blockIdx.x;
    const float* s; __half* d; int K, N;
    if (rem < 432)       { s = qkvw + (size_t)i * 442368; d = wt + (size_t)i * 1769472;           K = 384;  N = 1152; }
    else if (rem < 576)  { rem -= 432;  s = projw + (size_t)i * 147456; d = wt + (size_t)i * 1769472 + 442368;  K = 384;  N = 384;  }
    else if (rem < 1152) { rem -= 576;  s = fc1w  + (size_t)i * 589824; d = wt + (size_t)i * 1769472 + 589824;  K = 384;  N = 1536; }
    else                 { rem -= 1152; s = fc2w  + (size_t)i * 589824; d = wt + (size_t)i * 1769472 + 1179648; K = 1536; N = 384;  }
    int tilesX = N >> 5;
    int bx = (rem % tilesX) << 5, by = (rem / tilesX) << 5;
    int x = threadIdx.x & 31, y = threadIdx.x >> 5;
#pragma unroll
    for (int yy = y; yy < 32; yy += 8)
        tbuf[yy][x] = s[(size_t)(by + yy) * N + bx + x];
    __syncthreads();
#pragma unroll
    for (int yy = y; yy < 32; yy += 8)
        d[(size_t)(bx + yy) * K + by + x] = __float2half(tbuf[x][yy]);
}

// ---------------- LayerNorm, warp-per-token (8 tokens / 256-thr block) -----
template<int COPY>
__global__ __launch_bounds__(256)
void ln_warp(const float* __restrict__ x, const float* __restrict__ gw,
             const float* __restrict__ bw, __half* __restrict__ out,
             float* __restrict__ cpy)
{
    int warp = threadIdx.x >> 5, lane = threadIdx.x & 31;
    size_t tok = (size_t)blockIdx.x * 8 + warp;
    size_t base = tok * 384;
    float v[12];
    float s = 0.f, q = 0.f;
#pragma unroll
    for (int k = 0; k < 12; k++) {
        v[k] = x[base + lane + 32 * k];
        s += v[k];
        q += v[k] * v[k];
    }
#pragma unroll
    for (int o = 16; o > 0; o >>= 1) {
        s += __shfl_xor_sync(0xffffffffu, s, o);
        q += __shfl_xor_sync(0xffffffffu, q, o);
    }
    float mean = s * (1.0f / 384.0f);
    float var  = q * (1.0f / 384.0f) - mean * mean;
    float inv  = rsqrtf(var + 1e-5f);
#pragma unroll
    for (int k = 0; k < 12; k++) {
        int c = lane + 32 * k;
        out[base + c] = __float2half((v[k] - mean) * inv * gw[c] + bw[c]);
        if (COPY) cpy[base + c] = v[k];
    }
}

// ---------------- tensor-core windowed attention (P through smem) -----------
#define AQP 40
#define AVP 72
#define APP 72
#define AHEAD 7424
#define ARPS_OFF 59392
#define ATT_SMEM (59392 + 4 * 169 * 4)

__global__ __launch_bounds__(256, 3)
void attn_mma(const __half* __restrict__ qkv, const float* __restrict__ rpb,
              __half* __restrict__ o, int shift)
{
    extern __shared__ __align__(128) char smem[];
    __half* sh = (__half*)smem;
    float* rps = (float*)(smem + ARPS_OFF);
    uint32_t sb = smem_u32(smem);

    int tid = threadIdx.x, warp = tid >> 5, lane = tid & 31;
    int hg  = blockIdx.x % 3;
    int win = blockIdx.x / 3;
    int bimg = win >> 6, wi = (win >> 3) & 7, wj = win & 7;
    int head4 = warp >> 1;
    int head  = hg * 4 + head4;
    int mh    = warp & 1;
    int g = lane >> 2, t = lane & 3;
    int sub = lane >> 3, rr = lane & 7;

    for (int i = tid; i < ARPS_OFF / 16; i += 256)
        ((uint4*)smem)[i] = make_uint4(0, 0, 0, 0);
    for (int i = tid; i < 4 * 169; i += 256) {
        int h = i / 169, idx = i - h * 169;
        rps[i] = rpb[idx * 12 + hg * 4 + h];
    }
    __syncthreads();

    const __half2 sc2 = __floats2half2_rn(0.17677669529663687f, 0.17677669529663687f);
    for (int i = tid; i < 3136; i += 256) {
        int h = i / 784, rem = i - h * 784;
        int p = rem >> 4, d2 = rem & 15;
        int r = p / 7, c = p - r * 7;
        int hh = wi * 7 + r + shift; if (hh >= 56) hh -= 56;
        int ww = wj * 7 + c + shift; if (ww >= 56) ww -= 56;
        size_t gt = (size_t)bimg * 3136 + hh * 56 + ww;
        const __half2* bp = (const __half2*)(qkv + gt * 1152 + (hg * 4 + h) * 32) + d2;
        *(__half2*)&sh[h * AHEAD + p * AQP + d2 * 2] = __hmul2(bp[0], sc2);
        *(__half2*)&sh[h * AHEAD + 2560 + p * AQP + d2 * 2] = bp[192];
        __half2 vv = bp[384];
        sh[h * AHEAD + 5120 + (d2 * 2)     * AVP + p] = __low2half(vv);
        sh[h * AHEAD + 5120 + (d2 * 2 + 1) * AVP + p] = __high2half(vv);
    }
    __syncthreads();

    uint32_t qb = sb + (uint32_t)(head4 * AHEAD) * 2;
    uint32_t kb = sb + (uint32_t)(head4 * AHEAD + 2560) * 2;
    uint32_t vb = sb + (uint32_t)(head4 * AHEAD + 5120) * 2;

    float acc[2][8][4];
#pragma unroll
    for (int i = 0; i < 2; i++)
#pragma unroll
        for (int j = 0; j < 8; j++)
#pragma unroll
            for (int k = 0; k < 4; k++) acc[i][j][k] = 0.f;

#pragma unroll
    for (int ks = 0; ks < 2; ks++) {
        uint32_t a[2][4];
#pragma unroll
        for (int mt = 0; mt < 2; mt++)
            LDSM4(a[mt][0], a[mt][1], a[mt][2], a[mt][3],
                  qb + (uint32_t)(((mh * 32 + mt * 16 + (lane & 15)) * AQP + (lane >> 4) * 8) * 2) + ks * 32);
        uint32_t b[4][4];
#pragma unroll
        for (int np = 0; np < 4; np++)
            LDSM4(b[np][0], b[np][1], b[np][2], b[np][3],
                  kb + (uint32_t)((((sub >> 1) * 8 + rr) * AQP + (sub & 1) * 8) * 2) + np * (16 * AQP * 2) + ks * 32);
#pragma unroll
        for (int mt = 0; mt < 2; mt++)
#pragma unroll
            for (int nt = 0; nt < 8; nt++)
                MMA16816(acc[mt][nt], a[mt][0], a[mt][1], a[mt][2], a[mt][3],
                         b[nt >> 1][(nt & 1) * 2], b[nt >> 1][(nt & 1) * 2 + 1]);
    }

    int rpA[2][2], cpA[2][2], regpA[2][2], pvld[2][2];
#pragma unroll
    for (int mt = 0; mt < 2; mt++)
#pragma unroll
        for (int h8 = 0; h8 < 2; h8++) {
            int p = mh * 32 + mt * 16 + g + h8 * 8;
            pvld[mt][h8] = (p < 49);
            if (p < 49) {
                int rp = p / 7, cp = p - rp * 7;
                rpA[mt][h8] = rp; cpA[mt][h8] = cp;
                int hp = wi * 7 + rp, wp_ = wj * 7 + cp;
                regpA[mt][h8] = (hp < 49 ? 0 : (hp < 53 ? 1 : 2)) * 3 +
                                (wp_ < 49 ? 0 : (wp_ < 53 ? 1 : 2));
            } else { rpA[mt][h8] = 0; cpA[mt][h8] = 0; regpA[mt][h8] = 0; }
        }

#pragma unroll
    for (int nt = 0; nt < 8; nt++)
#pragma unroll
        for (int e = 0; e < 2; e++) {
            int j = nt * 8 + 2 * t + e;
            int rj = 0, cj = 0, regj = 0;
            int jv = (j < 49);
            if (jv) {
                rj = j / 7; cj = j - rj * 7;
                if (shift > 0) {
                    int hj = wi * 7 + rj, wq = wj * 7 + cj;
                    regj = (hj < 49 ? 0 : (hj < 53 ? 1 : 2)) * 3 +
                           (wq < 49 ? 0 : (wq < 53 ? 1 : 2));
                }
            }
#pragma unroll
            for (int mt = 0; mt < 2; mt++)
#pragma unroll
                for (int h8 = 0; h8 < 2; h8++) {
                    float s = acc[mt][nt][h8 * 2 + e];
                    if (jv && pvld[mt][h8]) {
                        s += rps[head4 * 169 + (rpA[mt][h8] - rj + 6) * 13 + (cpA[mt][h8] - cj + 6)];
                        if (shift > 0 && regpA[mt][h8] != regj) s -= 100.f;
                    }
                    if (!jv) s = -1e9f;
                    acc[mt][nt][h8 * 2 + e] = s;
                }
        }

    float inv[2][2];
#pragma unroll
    for (int mt = 0; mt < 2; mt++)
#pragma unroll
        for (int h8 = 0; h8 < 2; h8++) {
            float mx = -1e30f;
#pragma unroll
            for (int nt = 0; nt < 8; nt++) {
                mx = fmaxf(mx, acc[mt][nt][h8 * 2]);
                mx = fmaxf(mx, acc[mt][nt][h8 * 2 + 1]);
            }
            mx = fmaxf(mx, __shfl_xor_sync(0xffffffffu, mx, 1));
            mx = fmaxf(mx, __shfl_xor_sync(0xffffffffu, mx, 2));
            float sum = 0.f;
#pragma unroll
            for (int nt = 0; nt < 8; nt++) {
                float e0 = __expf(acc[mt][nt][h8 * 2] - mx);
                float e1 = __expf(acc[mt][nt][h8 * 2 + 1] - mx);
                acc[mt][nt][h8 * 2] = e0;
                acc[mt][nt][h8 * 2 + 1] = e1;
                sum += e0 + e1;
            }
            sum += __shfl_xor_sync(0xffffffffu, sum, 1);
            sum += __shfl_xor_sync(0xffffffffu, sum, 2);
            inv[mt][h8] = 1.f / sum;
        }

    asm volatile("bar.sync %0, %1;" :: "r"(head4 + 1), "r"(64) : "memory");

#pragma unroll
    for (int mt = 0; mt < 2; mt++)
#pragma unroll
        for (int h8 = 0; h8 < 2; h8++) {
            int prow = mh * 32 + mt * 16 + g + h8 * 8;
            float iv = inv[mt][h8];
#pragma unroll
            for (int nt = 0; nt < 8; nt++) {
                __half2 pv = __floats2half2_rn(acc[mt][nt][h8 * 2] * iv,
                                               acc[mt][nt][h8 * 2 + 1] * iv);
                *(__half2*)&sh[head4 * AHEAD + prow * APP + nt * 8 + 2 * t] = pv;
            }
        }
    __syncwarp();

    float o2[2][4][4];
#pragma unroll
    for (int i = 0; i < 2; i++)
#pragma unroll
        for (int j = 0; j < 4; j++)
#pragma unroll
            for (int k = 0; k < 4; k++) o2[i][j][k] = 0.f;

    uint32_t pb = sb + (uint32_t)(head4 * AHEAD) * 2;
#pragma unroll
    for (int ks = 0; ks < 4; ks++) {
        uint32_t a2[2][4];
#pragma unroll
        for (int mt = 0; mt < 2; mt++)
            LDSM4(a2[mt][0], a2[mt][1], a2[mt][2], a2[mt][3],
                  pb + (uint32_t)(((mh * 32 + mt * 16 + (lane & 15)) * APP + (lane >> 4) * 8) * 2) + ks * 32);
        uint32_t vb4[2][4];
#pragma unroll
        for (int np = 0; np < 2; np++)
            LDSM4(vb4[np][0], vb4[np][1], vb4[np][2], vb4[np][3],
                  vb + (uint32_t)((((sub >> 1) * 8 + rr) * AVP + (sub & 1) * 8) * 2) + np * (16 * AVP * 2) + ks * 32);
#pragma unroll
        for (int mt = 0; mt < 2; mt++)
#pragma unroll
            for (int nt = 0; nt < 4; nt++)
                MMA16816(o2[mt][nt], a2[mt][0], a2[mt][1], a2[mt][2], a2[mt][3],
                         vb4[nt >> 1][(nt & 1) * 2], vb4[nt >> 1][(nt & 1) * 2 + 1]);
    }

#pragma unroll
    for (int mt = 0; mt < 2; mt++)
#pragma unroll
        for (int h8 = 0; h8 < 2; h8++) {
            int p = mh * 32 + mt * 16 + g + h8 * 8;
            if (p < 49) {
                int r = p / 7, c = p - r * 7;
                int hh = wi * 7 + r + shift; if (hh >= 56) hh -= 56;
                int ww = wj * 7 + c + shift; if (ww >= 56) ww -= 56;
                size_t gt = (size_t)bimg * 3136 + hh * 56 + ww;
                __half* op = o + gt * 384 + head * 32;
#pragma unroll
                for (int nt = 0; nt < 4; nt++)
                    *(__half2*)&op[nt * 8 + 2 * t] =
                        __floats2half2_rn(o2[mt][nt][h8 * 2], o2[mt][nt][h8 * 2 + 1]);
            }
        }
}

// ---------------- launcher --------------------------------------------------
extern "C" void kernel_launch(void* const* d_in, const int* in_sizes, int n_in,
                              void* d_out, int out_size)
{
    const float* x     = (const float*)d_in[0];
    const float* n1g   = (const float*)d_in[1];
    const float* n1b   = (const float*)d_in[2];
    const float* qkvw  = (const float*)d_in[3];
    const float* qkvb  = (const float*)d_in[4];
    const float* rpb   = (const float*)d_in[5];
    const float* projw = (const float*)d_in[6];
    const float* projb = (const float*)d_in[7];
    const float* n2g   = (const float*)d_in[8];
    const float* n2b   = (const float*)d_in[9];
    const float* fc1w  = (const float*)d_in[10];
    const float* fc1b  = (const float*)d_in[11];
    const float* fc2w  = (const float*)d_in[12];
    const float* fc2b  = (const float*)d_in[13];
    float* out = (float*)d_out;

    __half *p_xn, *p_qkv, *p_o, *p_h1, *p_wt;
    cudaGetSymbolAddress((void**)&p_xn,  g_xn);
    cudaGetSymbolAddress((void**)&p_qkv, g_qkv);
    cudaGetSymbolAddress((void**)&p_o,   g_o);
    cudaGetSymbolAddress((void**)&p_h1,  g_h1);
    cudaGetSymbolAddress((void**)&p_wt,  g_wt);

    cudaFuncSetAttribute((void*)gemm_fp16<0, __half>, cudaFuncAttributeMaxDynamicSharedMemorySize, GEMM_SMEM);
    cudaFuncSetAttribute((void*)gemm_fp16<1, __half>, cudaFuncAttributeMaxDynamicSharedMemorySize, GEMM_SMEM);
    cudaFuncSetAttribute((void*)gemm_fp16<2, float>,  cudaFuncAttributeMaxDynamicSharedMemorySize, GEMM_SMEM);
    cudaFuncSetAttribute((void*)attn_mma, cudaFuncAttributeMaxDynamicSharedMemorySize, ATT_SMEM);

    transpose_all<<<1728, 256>>>(qkvw, projw, fc1w, fc2w, p_wt, 0);
    transpose_all<<<1728, 256>>>(qkvw, projw, fc1w, fc2w, p_wt, 1);

    for (int i = 0; i < 2; i++) {
        int shift = i ? 3 : 0;
        size_t base = (size_t)i * 1769472;
        if (i == 0)
            ln_warp<1><<<TOK / 8, 256>>>(x, n1g, n1b, p_xn, out);
        else
            ln_warp<0><<<TOK / 8, 256>>>(out, n1g + 384, n1b + 384, p_xn, nullptr);
        gemm_fp16<0, __half><<<dim3(9, 392), 256, GEMM_SMEM>>>(
            p_xn, p_wt + base, qkvb + i * 1152, p_qkv, 1152, 384);
        attn_mma<<<3072, 256, ATT_SMEM>>>(p_qkv, rpb + i * 169 * 12, p_o, shift);
        gemm_fp16<2, float><<<dim3(3, 392), 256, GEMM_SMEM>>>(
            p_o, p_wt + base + 442368, projb + i * 384, out, 384, 384);
        ln_warp<0><<<TOK / 8, 256>>>(out, n2g + i * 384, n2b + i * 384, p_xn, nullptr);
        gemm_fp16<1, __half><<<dim3(12, 392), 256, GEMM_SMEM>>>(
            p_xn, p_wt + base + 589824, fc1b + i * 1536, p_h1, 1536, 384);
        gemm_fp16<2, float><<<dim3(3, 392), 256, GEMM_SMEM>>>(
            p_h1, p_wt + base + 1179648, fc2b + i * 384, out, 384, 1536);
    }
}

// round 16
// speedup vs baseline: 1.0022x; 1.0022x over previous
#include <cuda_runtime.h>
#include <cuda_fp16.h>
#include <cstdint>
#include <math.h>

#define TOK 50176            // 16 * 56 * 56 tokens

// ---------------- scratch (device globals; no allocation allowed) ----------
__device__ __half g_xn [TOK * 384];    // LN output (fp16)
__device__ __half g_qkv[TOK * 1152];   // QKV activations (fp16)
__device__ __half g_o  [TOK * 384];    // attention output (fp16)
__device__ __half g_h1 [TOK * 1536];   // MLP hidden (fp16)
__device__ __half g_wt [2 * 1769472];  // transposed fp16 weights [N,K] per block

// ---------------- helpers ----------------------------------------------------
__device__ __forceinline__ void cp16s(uint32_t saddr, const void* g)
{
    asm volatile("cp.async.cg.shared.global [%0], [%1], 16;\n" :: "r"(saddr), "l"(g));
}
__device__ __forceinline__ uint32_t smem_u32(const void* p)
{
    uint32_t a;
    asm("{ .reg .u64 t; cvta.to.shared.u64 t, %1; cvt.u32.u64 %0, t; }" : "=r"(a) : "l"(p));
    return a;
}
#define LDSM4(r0, r1, r2, r3, addr) \
    asm volatile("ldmatrix.sync.aligned.m8n8.x4.shared.b16 {%0,%1,%2,%3}, [%4];" \
                 : "=r"(r0), "=r"(r1), "=r"(r2), "=r"(r3) : "r"(addr))
#define MMA16816(d, a0, a1, a2, a3, b0, b1) \
    asm volatile("mma.sync.aligned.m16n8k16.row.col.f32.f16.f16.f32 " \
                 "{%0,%1,%2,%3}, {%4,%5,%6,%7}, {%8,%9}, {%0,%1,%2,%3};\n" \
                 : "+f"((d)[0]), "+f"((d)[1]), "+f"((d)[2]), "+f"((d)[3]) \
                 : "r"(a0), "r"(a1), "r"(a2), "r"(a3), "r"(b0), "r"(b1))

// ---------------- fp16 tensor-core GEMM: BM=BN=128, warp tile 32x64 ---------
// 256 threads (4 warps M x 2 warps N), 3-stage cp.async, ONE barrier/iter.
// C[M,N] = A[M,K] @ Bt[N,K]^T + bias   (A,Bt fp16; accumulate fp32)
// MODE 0: store fp16   MODE 1: gelu -> fp16   MODE 2: fp32 residual add
#define BK 64
#define PITCH 72
#define STG_A (128 * PITCH * 2)        // 18432 B per operand per stage
#define STAGE (2 * STG_A)
#define SM_BIAS (3 * STAGE)
#define GEMM_SMEM (3 * STAGE + 512)    // 111104 B -> 2 CTAs/SM

template<int MODE, typename TOut>
__global__ __launch_bounds__(256, 2)
void gemm_fp16(const __half* __restrict__ A, const __half* __restrict__ Bt,
               const float* __restrict__ bias, TOut* __restrict__ Cout,
               int N, int K)
{
    extern __shared__ __align__(1024) char smem[];
    uint32_t sb = smem_u32(smem);
    float* bias_s = (float*)(smem + SM_BIAS);

    int tid  = threadIdx.x;
    int bn   = blockIdx.x, bm = blockIdx.y;
    int warp = tid >> 5, lane = tid & 31;
    int wm   = warp & 3;            // 4 warps along M (32 rows each)
    int wn   = warp >> 2;           // 2 warps along N (64 cols each)
    int g    = lane >> 2, t = lane & 3;
    int sub  = lane >> 3, r = lane & 7;

    if (tid < 128) bias_s[tid] = bias[bn * 128 + tid];

    float acc[2][8][4];
#pragma unroll
    for (int i = 0; i < 2; i++)
#pragma unroll
        for (int j = 0; j < 8; j++)
#pragma unroll
            for (int k = 0; k < 4; k++) acc[i][j][k] = 0.f;

    const __half* Ag = A  + (size_t)bm * 128 * K;
    const __half* Bg = Bt + (size_t)bn * 128 * K;

    // A,B: 128 rows x 8 chunks(16B) = 1024 each -> 4/thread each
    int ldrow = tid >> 1;                // 0..127
    int ldc0  = (tid & 1) * 4;           // 0 or 4

    uint32_t aoff = (uint32_t)(((wm * 32 + (lane & 15)) * PITCH + (lane >> 4) * 8) * 2);
    uint32_t boff = (uint32_t)(((wn * 64 + (sub >> 1) * 8 + r) * PITCH + (sub & 1) * 8) * 2);

    auto load_stage = [&](int stg, int kc) {
        uint32_t base = sb + (uint32_t)(stg * STAGE);
        int k0 = kc * BK;
#pragma unroll
        for (int c = 0; c < 4; c++) {
            uint32_t so = (uint32_t)(ldrow * PITCH + (ldc0 + c) * 8) * 2;
            cp16s(base + so,         Ag + (size_t)ldrow * K + k0 + (ldc0 + c) * 8);
            cp16s(base + STG_A + so, Bg + (size_t)ldrow * K + k0 + (ldc0 + c) * 8);
        }
    };

    int NK = K / BK;
    load_stage(0, 0);
    asm volatile("cp.async.commit_group;");
    load_stage(1, 1);
    asm volatile("cp.async.commit_group;");

    for (int kc = 0; kc < NK; kc++) {
        int buf = kc % 3;
        if (kc + 1 < NK) asm volatile("cp.async.wait_group 1;");
        else             asm volatile("cp.async.wait_group 0;");
        __syncthreads();
        if (kc + 2 < NK) {
            load_stage((kc + 2) % 3, kc + 2);
            asm volatile("cp.async.commit_group;");
        }

        uint32_t abase = sb + (uint32_t)(buf * STAGE) + aoff;
        uint32_t bbase = sb + (uint32_t)(buf * STAGE) + STG_A + boff;
#pragma unroll
        for (int ks = 0; ks < 4; ks++) {
            uint32_t a[2][4];
#pragma unroll
            for (int mt = 0; mt < 2; mt++)
                LDSM4(a[mt][0], a[mt][1], a[mt][2], a[mt][3],
                      abase + mt * (16 * PITCH * 2) + ks * 32);
            uint32_t b[4][4];
#pragma unroll
            for (int np = 0; np < 4; np++)
                LDSM4(b[np][0], b[np][1], b[np][2], b[np][3],
                      bbase + np * (16 * PITCH * 2) + ks * 32);
#pragma unroll
            for (int mt = 0; mt < 2; mt++)
#pragma unroll
                for (int nt = 0; nt < 8; nt++)
                    MMA16816(acc[mt][nt], a[mt][0], a[mt][1], a[mt][2], a[mt][3],
                             b[nt >> 1][(nt & 1) * 2], b[nt >> 1][(nt & 1) * 2 + 1]);
        }
    }

#pragma unroll
    for (int mt = 0; mt < 2; mt++) {
#pragma unroll
        for (int nt = 0; nt < 8; nt++) {
            int row = bm * 128 + wm * 32 + mt * 16 + g;
            int cl  = wn * 64 + nt * 8 + t * 2;
            int col = bn * 128 + cl;
            float b0 = bias_s[cl], b1 = bias_s[cl + 1];
            float v00 = acc[mt][nt][0] + b0, v01 = acc[mt][nt][1] + b1;
            float v10 = acc[mt][nt][2] + b0, v11 = acc[mt][nt][3] + b1;
            if (MODE == 1) {
                v00 = 0.5f * v00 * (1.f + erff(v00 * 0.70710678118654752f));
                v01 = 0.5f * v01 * (1.f + erff(v01 * 0.70710678118654752f));
                v10 = 0.5f * v10 * (1.f + erff(v10 * 0.70710678118654752f));
                v11 = 0.5f * v11 * (1.f + erff(v11 * 0.70710678118654752f));
            }
            size_t i0 = (size_t)row * N + col;
            size_t i1 = (size_t)(row + 8) * N + col;
            if (MODE == 2) {
                float* C = (float*)Cout;
                C[i0] += v00; C[i0 + 1] += v01;
                C[i1] += v10; C[i1 + 1] += v11;
            } else {
                __half* C = (__half*)Cout;
                *(__half2*)(C + i0) = __floats2half2_rn(v00, v01);
                *(__half2*)(C + i1) = __floats2half2_rn(v10, v11);
            }
        }
    }
}

// ---------------- fused weight transpose+convert (one launch per block i) --
__global__ __launch_bounds__(256)
void transpose_all(const float* __restrict__ qkvw, const float* __restrict__ projw,
                   const float* __restrict__ fc1w, const float* __restrict__ fc2w,
                   __half* __restrict__ wt, int i)
{
    __shared__ float tbuf[32][33];
    int rem = blockIdx.x;
    const float* s; __half* d; int K, N;
    if (rem < 432)       { s = qkvw + (size_t)i * 442368; d = wt + (size_t)i * 1769472;           K = 384;  N = 1152; }
    else if (rem < 576)  { rem -= 432;  s = projw + (size_t)i * 147456; d = wt + (size_t)i * 1769472 + 442368;  K = 384;  N = 384;  }
    else if (rem < 1152) { rem -= 576;  s = fc1w  + (size_t)i * 589824; d = wt + (size_t)i * 1769472 + 589824;  K = 384;  N = 1536; }
    else                 { rem -= 1152; s = fc2w  + (size_t)i * 589824; d = wt + (size_t)i * 1769472 + 1179648; K = 1536; N = 384;  }
    int tilesX = N >> 5;
    int bx = (rem % tilesX) << 5, by = (rem / tilesX) << 5;
    int x = threadIdx.x & 31, y = threadIdx.x >> 5;
#pragma unroll
    for (int yy = y; yy < 32; yy += 8)
        tbuf[yy][x] = s[(size_t)(by + yy) * N + bx + x];
    __syncthreads();
#pragma unroll
    for (int yy = y; yy < 32; yy += 8)
        d[(size_t)(bx + yy) * K + by + x] = __float2half(tbuf[x][yy]);
}

// ---------------- LayerNorm, warp-per-token (8 tokens / 256-thr block) -----
template<int COPY>
__global__ __launch_bounds__(256)
void ln_warp(const float* __restrict__ x, const float* __restrict__ gw,
             const float* __restrict__ bw, __half* __restrict__ out,
             float* __restrict__ cpy)
{
    int warp = threadIdx.x >> 5, lane = threadIdx.x & 31;
    size_t tok = (size_t)blockIdx.x * 8 + warp;
    size_t base = tok * 384;
    float v[12];
    float s = 0.f, q = 0.f;
#pragma unroll
    for (int k = 0; k < 12; k++) {
        v[k] = x[base + lane + 32 * k];
        s += v[k];
        q += v[k] * v[k];
    }
#pragma unroll
    for (int o = 16; o > 0; o >>= 1) {
        s += __shfl_xor_sync(0xffffffffu, s, o);
        q += __shfl_xor_sync(0xffffffffu, q, o);
    }
    float mean = s * (1.0f / 384.0f);
    float var  = q * (1.0f / 384.0f) - mean * mean;
    float inv  = rsqrtf(var + 1e-5f);
#pragma unroll
    for (int k = 0; k < 12; k++) {
        int c = lane + 32 * k;
        out[base + c] = __float2half((v[k] - mean) * inv * gw[c] + bw[c]);
        if (COPY) cpy[base + c] = v[k];
    }
}

// ---------------- tensor-core windowed attention (P through smem) -----------
#define AQP 40
#define AVP 72
#define APP 72
#define AHEAD 7424
#define ARPS_OFF 59392
#define ATT_SMEM (59392 + 4 * 169 * 4)

__global__ __launch_bounds__(256, 3)
void attn_mma(const __half* __restrict__ qkv, const float* __restrict__ rpb,
              __half* __restrict__ o, int shift)
{
    extern __shared__ __align__(128) char smem[];
    __half* sh = (__half*)smem;
    float* rps = (float*)(smem + ARPS_OFF);
    uint32_t sb = smem_u32(smem);

    int tid = threadIdx.x, warp = tid >> 5, lane = tid & 31;
    int hg  = blockIdx.x % 3;
    int win = blockIdx.x / 3;
    int bimg = win >> 6, wi = (win >> 3) & 7, wj = win & 7;
    int head4 = warp >> 1;
    int head  = hg * 4 + head4;
    int mh    = warp & 1;
    int g = lane >> 2, t = lane & 3;
    int sub = lane >> 3, rr = lane & 7;

    for (int i = tid; i < ARPS_OFF / 16; i += 256)
        ((uint4*)smem)[i] = make_uint4(0, 0, 0, 0);
    for (int i = tid; i < 4 * 169; i += 256) {
        int h = i / 169, idx = i - h * 169;
        rps[i] = rpb[idx * 12 + hg * 4 + h];
    }
    __syncthreads();

    const __half2 sc2 = __floats2half2_rn(0.17677669529663687f, 0.17677669529663687f);
    for (int i = tid; i < 3136; i += 256) {
        int h = i / 784, rem = i - h * 784;
        int p = rem >> 4, d2 = rem & 15;
        int r = p / 7, c = p - r * 7;
        int hh = wi * 7 + r + shift; if (hh >= 56) hh -= 56;
        int ww = wj * 7 + c + shift; if (ww >= 56) ww -= 56;
        size_t gt = (size_t)bimg * 3136 + hh * 56 + ww;
        const __half2* bp = (const __half2*)(qkv + gt * 1152 + (hg * 4 + h) * 32) + d2;
        *(__half2*)&sh[h * AHEAD + p * AQP + d2 * 2] = __hmul2(bp[0], sc2);
        *(__half2*)&sh[h * AHEAD + 2560 + p * AQP + d2 * 2] = bp[192];
        __half2 vv = bp[384];
        sh[h * AHEAD + 5120 + (d2 * 2)     * AVP + p] = __low2half(vv);
        sh[h * AHEAD + 5120 + (d2 * 2 + 1) * AVP + p] = __high2half(vv);
    }
    __syncthreads();

    uint32_t qb = sb + (uint32_t)(head4 * AHEAD) * 2;
    uint32_t kb = sb + (uint32_t)(head4 * AHEAD + 2560) * 2;
    uint32_t vb = sb + (uint32_t)(head4 * AHEAD + 5120) * 2;

    float acc[2][8][4];
#pragma unroll
    for (int i = 0; i < 2; i++)
#pragma unroll
        for (int j = 0; j < 8; j++)
#pragma unroll
            for (int k = 0; k < 4; k++) acc[i][j][k] = 0.f;

#pragma unroll
    for (int ks = 0; ks < 2; ks++) {
        uint32_t a[2][4];
#pragma unroll
        for (int mt = 0; mt < 2; mt++)
            LDSM4(a[mt][0], a[mt][1], a[mt][2], a[mt][3],
                  qb + (uint32_t)(((mh * 32 + mt * 16 + (lane & 15)) * AQP + (lane >> 4) * 8) * 2) + ks * 32);
        uint32_t b[4][4];
#pragma unroll
        for (int np = 0; np < 4; np++)
            LDSM4(b[np][0], b[np][1], b[np][2], b[np][3],
                  kb + (uint32_t)((((sub >> 1) * 8 + rr) * AQP + (sub & 1) * 8) * 2) + np * (16 * AQP * 2) + ks * 32);
#pragma unroll
        for (int mt = 0; mt < 2; mt++)
#pragma unroll
            for (int nt = 0; nt < 8; nt++)
                MMA16816(acc[mt][nt], a[mt][0], a[mt][1], a[mt][2], a[mt][3],
                         b[nt >> 1][(nt & 1) * 2], b[nt >> 1][(nt & 1) * 2 + 1]);
    }

    int rpA[2][2], cpA[2][2], regpA[2][2], pvld[2][2];
#pragma unroll
    for (int mt = 0; mt < 2; mt++)
#pragma unroll
        for (int h8 = 0; h8 < 2; h8++) {
            int p = mh * 32 + mt * 16 + g + h8 * 8;
            pvld[mt][h8] = (p < 49);
            if (p < 49) {
                int rp = p / 7, cp = p - rp * 7;
                rpA[mt][h8] = rp; cpA[mt][h8] = cp;
                int hp = wi * 7 + rp, wp_ = wj * 7 + cp;
                regpA[mt][h8] = (hp < 49 ? 0 : (hp < 53 ? 1 : 2)) * 3 +
                                (wp_ < 49 ? 0 : (wp_ < 53 ? 1 : 2));
            } else { rpA[mt][h8] = 0; cpA[mt][h8] = 0; regpA[mt][h8] = 0; }
        }

#pragma unroll
    for (int nt = 0; nt < 8; nt++)
#pragma unroll
        for (int e = 0; e < 2; e++) {
            int j = nt * 8 + 2 * t + e;
            int rj = 0, cj = 0, regj = 0;
            int jv = (j < 49);
            if (jv) {
                rj = j / 7; cj = j - rj * 7;
                if (shift > 0) {
                    int hj = wi * 7 + rj, wq = wj * 7 + cj;
                    regj = (hj < 49 ? 0 : (hj < 53 ? 1 : 2)) * 3 +
                           (wq < 49 ? 0 : (wq < 53 ? 1 : 2));
                }
            }
#pragma unroll
            for (int mt = 0; mt < 2; mt++)
#pragma unroll
                for (int h8 = 0; h8 < 2; h8++) {
                    float s = acc[mt][nt][h8 * 2 + e];
                    if (jv && pvld[mt][h8]) {
                        s += rps[head4 * 169 + (rpA[mt][h8] - rj + 6) * 13 + (cpA[mt][h8] - cj + 6)];
                        if (shift > 0 && regpA[mt][h8] != regj) s -= 100.f;
                    }
                    if (!jv) s = -1e9f;
                    acc[mt][nt][h8 * 2 + e] = s;
                }
        }

    float inv[2][2];
#pragma unroll
    for (int mt = 0; mt < 2; mt++)
#pragma unroll
        for (int h8 = 0; h8 < 2; h8++) {
            float mx = -1e30f;
#pragma unroll
            for (int nt = 0; nt < 8; nt++) {
                mx = fmaxf(mx, acc[mt][nt][h8 * 2]);
                mx = fmaxf(mx, acc[mt][nt][h8 * 2 + 1]);
            }
            mx = fmaxf(mx, __shfl_xor_sync(0xffffffffu, mx, 1));
            mx = fmaxf(mx, __shfl_xor_sync(0xffffffffu, mx, 2));
            float sum = 0.f;
#pragma unroll
            for (int nt = 0; nt < 8; nt++) {
                float e0 = __expf(acc[mt][nt][h8 * 2] - mx);
                float e1 = __expf(acc[mt][nt][h8 * 2 + 1] - mx);
                acc[mt][nt][h8 * 2] = e0;
                acc[mt][nt][h8 * 2 + 1] = e1;
                sum += e0 + e1;
            }
            sum += __shfl_xor_sync(0xffffffffu, sum, 1);
            sum += __shfl_xor_sync(0xffffffffu, sum, 2);
            inv[mt][h8] = 1.f / sum;
        }

    asm volatile("bar.sync %0, %1;" :: "r"(head4 + 1), "r"(64) : "memory");

#pragma unroll
    for (int mt = 0; mt < 2; mt++)
#pragma unroll
        for (int h8 = 0; h8 < 2; h8++) {
            int prow = mh * 32 + mt * 16 + g + h8 * 8;
            float iv = inv[mt][h8];
#pragma unroll
            for (int nt = 0; nt < 8; nt++) {
                __half2 pv = __floats2half2_rn(acc[mt][nt][h8 * 2] * iv,
                                               acc[mt][nt][h8 * 2 + 1] * iv);
                *(__half2*)&sh[head4 * AHEAD + prow * APP + nt * 8 + 2 * t] = pv;
            }
        }
    __syncwarp();

    float o2[2][4][4];
#pragma unroll
    for (int i = 0; i < 2; i++)
#pragma unroll
        for (int j = 0; j < 4; j++)
#pragma unroll
            for (int k = 0; k < 4; k++) o2[i][j][k] = 0.f;

    uint32_t pb = sb + (uint32_t)(head4 * AHEAD) * 2;
#pragma unroll
    for (int ks = 0; ks < 4; ks++) {
        uint32_t a2[2][4];
#pragma unroll
        for (int mt = 0; mt < 2; mt++)
            LDSM4(a2[mt][0], a2[mt][1], a2[mt][2], a2[mt][3],
                  pb + (uint32_t)(((mh * 32 + mt * 16 + (lane & 15)) * APP + (lane >> 4) * 8) * 2) + ks * 32);
        uint32_t vb4[2][4];
#pragma unroll
        for (int np = 0; np < 2; np++)
            LDSM4(vb4[np][0], vb4[np][1], vb4[np][2], vb4[np][3],
                  vb + (uint32_t)((((sub >> 1) * 8 + rr) * AVP + (sub & 1) * 8) * 2) + np * (16 * AVP * 2) + ks * 32);
#pragma unroll
        for (int mt = 0; mt < 2; mt++)
#pragma unroll
            for (int nt = 0; nt < 4; nt++)
                MMA16816(o2[mt][nt], a2[mt][0], a2[mt][1], a2[mt][2], a2[mt][3],
                         vb4[nt >> 1][(nt & 1) * 2], vb4[nt >> 1][(nt & 1) * 2 + 1]);
    }

#pragma unroll
    for (int mt = 0; mt < 2; mt++)
#pragma unroll
        for (int h8 = 0; h8 < 2; h8++) {
            int p = mh * 32 + mt * 16 + g + h8 * 8;
            if (p < 49) {
                int r = p / 7, c = p - r * 7;
                int hh = wi * 7 + r + shift; if (hh >= 56) hh -= 56;
                int ww = wj * 7 + c + shift; if (ww >= 56) ww -= 56;
                size_t gt = (size_t)bimg * 3136 + hh * 56 + ww;
                __half* op = o + gt * 384 + head * 32;
#pragma unroll
                for (int nt = 0; nt < 4; nt++)
                    *(__half2*)&op[nt * 8 + 2 * t] =
                        __floats2half2_rn(o2[mt][nt][h8 * 2], o2[mt][nt][h8 * 2 + 1]);
            }
        }
}

// ---------------- launcher --------------------------------------------------
extern "C" void kernel_launch(void* const* d_in, const int* in_sizes, int n_in,
                              void* d_out, int out_size)
{
    const float* x     = (const float*)d_in[0];
    const float* n1g   = (const float*)d_in[1];
    const float* n1b   = (const float*)d_in[2];
    const float* qkvw  = (const float*)d_in[3];
    const float* qkvb  = (const float*)d_in[4];
    const float* rpb   = (const float*)d_in[5];
    const float* projw = (const float*)d_in[6];
    const float* projb = (const float*)d_in[7];
    const float* n2g   = (const float*)d_in[8];
    const float* n2b   = (const float*)d_in[9];
    const float* fc1w  = (const float*)d_in[10];
    const float* fc1b  = (const float*)d_in[11];
    const float* fc2w  = (const float*)d_in[12];
    const float* fc2b  = (const float*)d_in[13];
    float* out = (float*)d_out;

    __half *p_xn, *p_qkv, *p_o, *p_h1, *p_wt;
    cudaGetSymbolAddress((void**)&p_xn,  g_xn);
    cudaGetSymbolAddress((void**)&p_qkv, g_qkv);
    cudaGetSymbolAddress((void**)&p_o,   g_o);
    cudaGetSymbolAddress((void**)&p_h1,  g_h1);
    cudaGetSymbolAddress((void**)&p_wt,  g_wt);

    cudaFuncSetAttribute((void*)gemm_fp16<0, __half>, cudaFuncAttributeMaxDynamicSharedMemorySize, GEMM_SMEM);
    cudaFuncSetAttribute((void*)gemm_fp16<1, __half>, cudaFuncAttributeMaxDynamicSharedMemorySize, GEMM_SMEM);
    cudaFuncSetAttribute((void*)gemm_fp16<2, float>,  cudaFuncAttributeMaxDynamicSharedMemorySize, GEMM_SMEM);
    cudaFuncSetAttribute((void*)attn_mma, cudaFuncAttributeMaxDynamicSharedMemorySize, ATT_SMEM);

    transpose_all<<<1728, 256>>>(qkvw, projw, fc1w, fc2w, p_wt, 0);
    transpose_all<<<1728, 256>>>(qkvw, projw, fc1w, fc2w, p_wt, 1);

    for (int i = 0; i < 2; i++) {
        int shift = i ? 3 : 0;
        size_t base = (size_t)i * 1769472;
        if (i == 0)
            ln_warp<1><<<TOK / 8, 256>>>(x, n1g, n1b, p_xn, out);
        else
            ln_warp<0><<<TOK / 8, 256>>>(out, n1g + 384, n1b + 384, p_xn, nullptr);
        gemm_fp16<0, __half><<<dim3(9, 392), 256, GEMM_SMEM>>>(
            p_xn, p_wt + base, qkvb + i * 1152, p_qkv, 1152, 384);
        attn_mma<<<3072, 256, ATT_SMEM>>>(p_qkv, rpb + i * 169 * 12, p_o, shift);
        gemm_fp16<2, float><<<dim3(3, 392), 256, GEMM_SMEM>>>(
            p_o, p_wt + base + 442368, projb + i * 384, out, 384, 384);
        ln_warp<0><<<TOK / 8, 256>>>(out, n2g + i * 384, n2b + i * 384, p_xn, nullptr);
        gemm_fp16<1, __half><<<dim3(12, 392), 256, GEMM_SMEM>>>(
            p_xn, p_wt + base + 589824, fc1b + i * 1536, p_h1, 1536, 384);
        gemm_fp16<2, float><<<dim3(3, 392), 256, GEMM_SMEM>>>(
            p_h1, p_wt + base + 1179648, fc2b + i * 384, out, 384, 1536);
    }
}

// round 17
// speedup vs baseline: 1.2204x; 1.2178x over previous
#include <cuda_runtime.h>
#include <cuda_fp16.h>
#include <cstdint>
#include <math.h>

#define TOK 50176            // 16 * 56 * 56 tokens

// ---------------- scratch (device globals; no allocation allowed) ----------
__device__ __half g_xn [TOK * 384];    // LN output (fp16)
__device__ __half g_qkv[TOK * 1152];   // QKV activations (fp16)
__device__ __half g_o  [TOK * 384];    // attention output (fp16)
__device__ __half g_h1 [TOK * 1536];   // MLP hidden (fp16)
__device__ __half g_wt [2 * 1769472];  // transposed fp16 weights [N,K] per block

// ---------------- helpers ----------------------------------------------------
__device__ __forceinline__ void cp16s(uint32_t saddr, const void* g)      // L1-bypass
{
    asm volatile("cp.async.cg.shared.global [%0], [%1], 16;\n" :: "r"(saddr), "l"(g));
}
__device__ __forceinline__ void cp16sa(uint32_t saddr, const void* g)     // L1-cached
{
    asm volatile("cp.async.ca.shared.global [%0], [%1], 16;\n" :: "r"(saddr), "l"(g));
}
__device__ __forceinline__ uint32_t smem_u32(const void* p)
{
    uint32_t a;
    asm("{ .reg .u64 t; cvta.to.shared.u64 t, %1; cvt.u32.u64 %0, t; }" : "=r"(a) : "l"(p));
    return a;
}
#define LDSM4(r0, r1, r2, r3, addr) \
    asm volatile("ldmatrix.sync.aligned.m8n8.x4.shared.b16 {%0,%1,%2,%3}, [%4];" \
                 : "=r"(r0), "=r"(r1), "=r"(r2), "=r"(r3) : "r"(addr))
#define MMA16816(d, a0, a1, a2, a3, b0, b1) \
    asm volatile("mma.sync.aligned.m16n8k16.row.col.f32.f16.f16.f32 " \
                 "{%0,%1,%2,%3}, {%4,%5,%6,%7}, {%8,%9}, {%0,%1,%2,%3};\n" \
                 : "+f"((d)[0]), "+f"((d)[1]), "+f"((d)[2]), "+f"((d)[3]) \
                 : "r"(a0), "r"(a1), "r"(a2), "r"(a3), "r"(b0), "r"(b1))

// ---------------- fp16 tensor-core GEMM: BM=BN=128, warp tile 32x32 ---------
// 512 threads (4x4 warps), 3-stage cp.async, ONE barrier per iteration.
#define BK 64
#define PITCH 72
#define STG_A (128 * PITCH * 2)        // 18432 B per operand per stage
#define STAGE (2 * STG_A)
#define SM_BIAS (3 * STAGE)
#define GEMM_SMEM (3 * STAGE + 512)    // 111104 B -> 2 CTAs/SM

template<int MODE, typename TOut>
__global__ __launch_bounds__(512, 2)
void gemm_fp16(const __half* __restrict__ A, const __half* __restrict__ Bt,
               const float* __restrict__ bias, TOut* __restrict__ Cout,
               int N, int K)
{
    extern __shared__ __align__(1024) char smem[];
    uint32_t sb = smem_u32(smem);
    float* bias_s = (float*)(smem + SM_BIAS);

    int tid  = threadIdx.x;
    int bn   = blockIdx.x, bm = blockIdx.y;
    int warp = tid >> 5, lane = tid & 31;
    int wm   = warp & 3;
    int wn   = warp >> 2;
    int g    = lane >> 2, t = lane & 3;
    int sub  = lane >> 3, r = lane & 7;

    if (tid < 128) bias_s[tid] = bias[bn * 128 + tid];

    float acc[2][4][4];
#pragma unroll
    for (int i = 0; i < 2; i++)
#pragma unroll
        for (int j = 0; j < 4; j++)
#pragma unroll
            for (int k = 0; k < 4; k++) acc[i][j][k] = 0.f;

    const __half* Ag = A  + (size_t)bm * 128 * K;
    const __half* Bg = Bt + (size_t)bn * 128 * K;

    int ldrow = tid >> 2;
    int ldc0  = (tid & 3) * 2;

    uint32_t aoff = (uint32_t)(((wm * 32 + (lane & 15)) * PITCH + (lane >> 4) * 8) * 2);
    uint32_t boff = (uint32_t)(((wn * 32 + (sub >> 1) * 8 + r) * PITCH + (sub & 1) * 8) * 2);

    auto load_stage = [&](int stg, int kc) {
        uint32_t base = sb + (uint32_t)(stg * STAGE);
        int k0 = kc * BK;
#pragma unroll
        for (int c = 0; c < 2; c++) {
            uint32_t so = (uint32_t)(ldrow * PITCH + (ldc0 + c) * 8) * 2;
            cp16sa(base + so,         Ag + (size_t)ldrow * K + k0 + (ldc0 + c) * 8);  // A: L1-cached (shared by co-resident CTA)
            cp16s (base + STG_A + so, Bg + (size_t)ldrow * K + k0 + (ldc0 + c) * 8);  // B: bypass
        }
    };

    int NK = K / BK;
    load_stage(0, 0);
    asm volatile("cp.async.commit_group;");
    load_stage(1, 1);
    asm volatile("cp.async.commit_group;");

    for (int kc = 0; kc < NK; kc++) {
        int buf = kc % 3;
        if (kc + 1 < NK) asm volatile("cp.async.wait_group 1;");
        else             asm volatile("cp.async.wait_group 0;");
        __syncthreads();
        if (kc + 2 < NK) {
            load_stage((kc + 2) % 3, kc + 2);
            asm volatile("cp.async.commit_group;");
        }

        uint32_t abase = sb + (uint32_t)(buf * STAGE) + aoff;
        uint32_t bbase = sb + (uint32_t)(buf * STAGE) + STG_A + boff;
#pragma unroll
        for (int ks = 0; ks < 4; ks++) {
            uint32_t a[2][4];
#pragma unroll
            for (int mt = 0; mt < 2; mt++)
                LDSM4(a[mt][0], a[mt][1], a[mt][2], a[mt][3],
                      abase + mt * (16 * PITCH * 2) + ks * 32);
            uint32_t b[2][4];
#pragma unroll
            for (int np = 0; np < 2; np++)
                LDSM4(b[np][0], b[np][1], b[np][2], b[np][3],
                      bbase + np * (16 * PITCH * 2) + ks * 32);
#pragma unroll
            for (int mt = 0; mt < 2; mt++)
#pragma unroll
                for (int nt = 0; nt < 4; nt++)
                    MMA16816(acc[mt][nt], a[mt][0], a[mt][1], a[mt][2], a[mt][3],
                             b[nt >> 1][(nt & 1) * 2], b[nt >> 1][(nt & 1) * 2 + 1]);
        }
    }

#pragma unroll
    for (int mt = 0; mt < 2; mt++) {
#pragma unroll
        for (int nt = 0; nt < 4; nt++) {
            int row = bm * 128 + wm * 32 + mt * 16 + g;
            int cl  = wn * 32 + nt * 8 + t * 2;
            int col = bn * 128 + cl;
            float b0 = bias_s[cl], b1 = bias_s[cl + 1];
            float v00 = acc[mt][nt][0] + b0, v01 = acc[mt][nt][1] + b1;
            float v10 = acc[mt][nt][2] + b0, v11 = acc[mt][nt][3] + b1;
            if (MODE == 1) {
                v00 = 0.5f * v00 * (1.f + erff(v00 * 0.70710678118654752f));
                v01 = 0.5f * v01 * (1.f + erff(v01 * 0.70710678118654752f));
                v10 = 0.5f * v10 * (1.f + erff(v10 * 0.70710678118654752f));
                v11 = 0.5f * v11 * (1.f + erff(v11 * 0.70710678118654752f));
            }
            size_t i0 = (size_t)row * N + col;
            size_t i1 = (size_t)(row + 8) * N + col;
            if (MODE == 2) {
                float2* C0 = (float2*)((float*)Cout + i0);
                float2* C1 = (float2*)((float*)Cout + i1);
                float2 o0 = *C0, o1 = *C1;
                o0.x += v00; o0.y += v01;
                o1.x += v10; o1.y += v11;
                *C0 = o0; *C1 = o1;
            } else {
                __half* C = (__half*)Cout;
                *(__half2*)(C + i0) = __floats2half2_rn(v00, v01);
                *(__half2*)(C + i1) = __floats2half2_rn(v10, v11);
            }
        }
    }
}

// ---------------- fused weight transpose+convert (one launch per block i) --
__global__ __launch_bounds__(256)
void transpose_all(const float* __restrict__ qkvw, const float* __restrict__ projw,
                   const float* __restrict__ fc1w, const float* __restrict__ fc2w,
                   __half* __restrict__ wt, int i)
{
    __shared__ float tbuf[32][33];
    int rem = blockIdx.x;
    const float* s; __half* d; int K, N;
    if (rem < 432)       { s = qkvw + (size_t)i * 442368; d = wt + (size_t)i * 1769472;           K = 384;  N = 1152; }
    else if (rem < 576)  { rem -= 432;  s = projw + (size_t)i * 147456; d = wt + (size_t)i * 1769472 + 442368;  K = 384;  N = 384;  }
    else if (rem < 1152) { rem -= 576;  s = fc1w  + (size_t)i * 589824; d = wt + (size_t)i * 1769472 + 589824;  K = 384;  N = 1536; }
    else                 { rem -= 1152; s = fc2w  + (size_t)i * 589824; d = wt + (size_t)i * 1769472 + 1179648; K = 1536; N = 384;  }
    int tilesX = N >> 5;
    int bx = (rem % tilesX) << 5, by = (rem / tilesX) << 5;
    int x = threadIdx.x & 31, y = threadIdx.x >> 5;
#pragma unroll
    for (int yy = y; yy < 32; yy += 8)
        tbuf[yy][x] = s[(size_t)(by + yy) * N + bx + x];
    __syncthreads();
#pragma unroll
    for (int yy = y; yy < 32; yy += 8)
        d[(size_t)(bx + yy) * K + by + x] = __float2half(tbuf[x][yy]);
}

// ---------------- LayerNorm, warp-per-token (8 tokens / 256-thr block) -----
template<int COPY>
__global__ __launch_bounds__(256)
void ln_warp(const float* __restrict__ x, const float* __restrict__ gw,
             const float* __restrict__ bw, __half* __restrict__ out,
             float* __restrict__ cpy)
{
    int warp = threadIdx.x >> 5, lane = threadIdx.x & 31;
    size_t tok = (size_t)blockIdx.x * 8 + warp;
    size_t base = tok * 384;
    float v[12];
    float s = 0.f, q = 0.f;
#pragma unroll
    for (int k = 0; k < 12; k++) {
        v[k] = x[base + lane + 32 * k];
        s += v[k];
        q += v[k] * v[k];
    }
#pragma unroll
    for (int o = 16; o > 0; o >>= 1) {
        s += __shfl_xor_sync(0xffffffffu, s, o);
        q += __shfl_xor_sync(0xffffffffu, q, o);
    }
    float mean = s * (1.0f / 384.0f);
    float var  = q * (1.0f / 384.0f) - mean * mean;
    float inv  = rsqrtf(var + 1e-5f);
#pragma unroll
    for (int k = 0; k < 12; k++) {
        int c = lane + 32 * k;
        out[base + c] = __float2half((v[k] - mean) * inv * gw[c] + bw[c]);
        if (COPY) cpy[base + c] = v[k];
    }
}

// ---------------- tensor-core windowed attention (P through smem) -----------
#define AQP 40
#define AVP 72
#define APP 72
#define AHEAD 7424
#define ARPS_OFF 59392
#define ATT_SMEM (59392 + 4 * 169 * 4)

__global__ __launch_bounds__(256, 3)
void attn_mma(const __half* __restrict__ qkv, const float* __restrict__ rpb,
              __half* __restrict__ o, int shift)
{
    extern __shared__ __align__(128) char smem[];
    __half* sh = (__half*)smem;
    float* rps = (float*)(smem + ARPS_OFF);
    uint32_t sb = smem_u32(smem);

    int tid = threadIdx.x, warp = tid >> 5, lane = tid & 31;
    int hg  = blockIdx.x % 3;
    int win = blockIdx.x / 3;
    int bimg = win >> 6, wi = (win >> 3) & 7, wj = win & 7;
    int head4 = warp >> 1;
    int head  = hg * 4 + head4;
    int mh    = warp & 1;
    int g = lane >> 2, t = lane & 3;
    int sub = lane >> 3, rr = lane & 7;

    for (int i = tid; i < ARPS_OFF / 16; i += 256)
        ((uint4*)smem)[i] = make_uint4(0, 0, 0, 0);
    for (int i = tid; i < 4 * 169; i += 256) {
        int h = i / 169, idx = i - h * 169;
        rps[i] = rpb[idx * 12 + hg * 4 + h];
    }
    __syncthreads();

    const __half2 sc2 = __floats2half2_rn(0.17677669529663687f, 0.17677669529663687f);
    for (int i = tid; i < 3136; i += 256) {
        int h = i / 784, rem = i - h * 784;
        int p = rem >> 4, d2 = rem & 15;
        int r = p / 7, c = p - r * 7;
        int hh = wi * 7 + r + shift; if (hh >= 56) hh -= 56;
        int ww = wj * 7 + c + shift; if (ww >= 56) ww -= 56;
        size_t gt = (size_t)bimg * 3136 + hh * 56 + ww;
        const __half2* bp = (const __half2*)(qkv + gt * 1152 + (hg * 4 + h) * 32) + d2;
        *(__half2*)&sh[h * AHEAD + p * AQP + d2 * 2] = __hmul2(bp[0], sc2);
        *(__half2*)&sh[h * AHEAD + 2560 + p * AQP + d2 * 2] = bp[192];
        __half2 vv = bp[384];
        sh[h * AHEAD + 5120 + (d2 * 2)     * AVP + p] = __low2half(vv);
        sh[h * AHEAD + 5120 + (d2 * 2 + 1) * AVP + p] = __high2half(vv);
    }
    __syncthreads();

    uint32_t qb = sb + (uint32_t)(head4 * AHEAD) * 2;
    uint32_t kb = sb + (uint32_t)(head4 * AHEAD + 2560) * 2;
    uint32_t vb = sb + (uint32_t)(head4 * AHEAD + 5120) * 2;

    float acc[2][8][4];
#pragma unroll
    for (int i = 0; i < 2; i++)
#pragma unroll
        for (int j = 0; j < 8; j++)
#pragma unroll
            for (int k = 0; k < 4; k++) acc[i][j][k] = 0.f;

#pragma unroll
    for (int ks = 0; ks < 2; ks++) {
        uint32_t a[2][4];
#pragma unroll
        for (int mt = 0; mt < 2; mt++)
            LDSM4(a[mt][0], a[mt][1], a[mt][2], a[mt][3],
                  qb + (uint32_t)(((mh * 32 + mt * 16 + (lane & 15)) * AQP + (lane >> 4) * 8) * 2) + ks * 32);
        uint32_t b[4][4];
#pragma unroll
        for (int np = 0; np < 4; np++)
            LDSM4(b[np][0], b[np][1], b[np][2], b[np][3],
                  kb + (uint32_t)((((sub >> 1) * 8 + rr) * AQP + (sub & 1) * 8) * 2) + np * (16 * AQP * 2) + ks * 32);
#pragma unroll
        for (int mt = 0; mt < 2; mt++)
#pragma unroll
            for (int nt = 0; nt < 8; nt++)
                MMA16816(acc[mt][nt], a[mt][0], a[mt][1], a[mt][2], a[mt][3],
                         b[nt >> 1][(nt & 1) * 2], b[nt >> 1][(nt & 1) * 2 + 1]);
    }

    int rpA[2][2], cpA[2][2], regpA[2][2], pvld[2][2];
#pragma unroll
    for (int mt = 0; mt < 2; mt++)
#pragma unroll
        for (int h8 = 0; h8 < 2; h8++) {
            int p = mh * 32 + mt * 16 + g + h8 * 8;
            pvld[mt][h8] = (p < 49);
            if (p < 49) {
                int rp = p / 7, cp = p - rp * 7;
                rpA[mt][h8] = rp; cpA[mt][h8] = cp;
                int hp = wi * 7 + rp, wp_ = wj * 7 + cp;
                regpA[mt][h8] = (hp < 49 ? 0 : (hp < 53 ? 1 : 2)) * 3 +
                                (wp_ < 49 ? 0 : (wp_ < 53 ? 1 : 2));
            } else { rpA[mt][h8] = 0; cpA[mt][h8] = 0; regpA[mt][h8] = 0; }
        }

#pragma unroll
    for (int nt = 0; nt < 8; nt++)
#pragma unroll
        for (int e = 0; e < 2; e++) {
            int j = nt * 8 + 2 * t + e;
            int rj = 0, cj = 0, regj = 0;
            int jv = (j < 49);
            if (jv) {
                rj = j / 7; cj = j - rj * 7;
                if (shift > 0) {
                    int hj = wi * 7 + rj, wq = wj * 7 + cj;
                    regj = (hj < 49 ? 0 : (hj < 53 ? 1 : 2)) * 3 +
                           (wq < 49 ? 0 : (wq < 53 ? 1 : 2));
                }
            }
#pragma unroll
            for (int mt = 0; mt < 2; mt++)
#pragma unroll
                for (int h8 = 0; h8 < 2; h8++) {
                    float s = acc[mt][nt][h8 * 2 + e];
                    if (jv && pvld[mt][h8]) {
                        s += rps[head4 * 169 + (rpA[mt][h8] - rj + 6) * 13 + (cpA[mt][h8] - cj + 6)];
                        if (shift > 0 && regpA[mt][h8] != regj) s -= 100.f;
                    }
                    if (!jv) s = -1e9f;
                    acc[mt][nt][h8 * 2 + e] = s;
                }
        }

    float inv[2][2];
#pragma unroll
    for (int mt = 0; mt < 2; mt++)
#pragma unroll
        for (int h8 = 0; h8 < 2; h8++) {
            float mx = -1e30f;
#pragma unroll
            for (int nt = 0; nt < 8; nt++) {
                mx = fmaxf(mx, acc[mt][nt][h8 * 2]);
                mx = fmaxf(mx, acc[mt][nt][h8 * 2 + 1]);
            }
            mx = fmaxf(mx, __shfl_xor_sync(0xffffffffu, mx, 1));
            mx = fmaxf(mx, __shfl_xor_sync(0xffffffffu, mx, 2));
            float sum = 0.f;
#pragma unroll
            for (int nt = 0; nt < 8; nt++) {
                float e0 = __expf(acc[mt][nt][h8 * 2] - mx);
                float e1 = __expf(acc[mt][nt][h8 * 2 + 1] - mx);
                acc[mt][nt][h8 * 2] = e0;
                acc[mt][nt][h8 * 2 + 1] = e1;
                sum += e0 + e1;
            }
            sum += __shfl_xor_sync(0xffffffffu, sum, 1);
            sum += __shfl_xor_sync(0xffffffffu, sum, 2);
            inv[mt][h8] = 1.f / sum;
        }

    asm volatile("bar.sync %0, %1;" :: "r"(head4 + 1), "r"(64) : "memory");

#pragma unroll
    for (int mt = 0; mt < 2; mt++)
#pragma unroll
        for (int h8 = 0; h8 < 2; h8++) {
            int prow = mh * 32 + mt * 16 + g + h8 * 8;
            float iv = inv[mt][h8];
#pragma unroll
            for (int nt = 0; nt < 8; nt++) {
                __half2 pv = __floats2half2_rn(acc[mt][nt][h8 * 2] * iv,
                                               acc[mt][nt][h8 * 2 + 1] * iv);
                *(__half2*)&sh[head4 * AHEAD + prow * APP + nt * 8 + 2 * t] = pv;
            }
        }
    __syncwarp();

    float o2[2][4][4];
#pragma unroll
    for (int i = 0; i < 2; i++)
#pragma unroll
        for (int j = 0; j < 4; j++)
#pragma unroll
            for (int k = 0; k < 4; k++) o2[i][j][k] = 0.f;

    uint32_t pb = sb + (uint32_t)(head4 * AHEAD) * 2;
#pragma unroll
    for (int ks = 0; ks < 4; ks++) {
        uint32_t a2[2][4];
#pragma unroll
        for (int mt = 0; mt < 2; mt++)
            LDSM4(a2[mt][0], a2[mt][1], a2[mt][2], a2[mt][3],
                  pb + (uint32_t)(((mh * 32 + mt * 16 + (lane & 15)) * APP + (lane >> 4) * 8) * 2) + ks * 32);
        uint32_t vb4[2][4];
#pragma unroll
        for (int np = 0; np < 2; np++)
            LDSM4(vb4[np][0], vb4[np][1], vb4[np][2], vb4[np][3],
                  vb + (uint32_t)((((sub >> 1) * 8 + rr) * AVP + (sub & 1) * 8) * 2) + np * (16 * AVP * 2) + ks * 32);
#pragma unroll
        for (int mt = 0; mt < 2; mt++)
#pragma unroll
            for (int nt = 0; nt < 4; nt++)
                MMA16816(o2[mt][nt], a2[mt][0], a2[mt][1], a2[mt][2], a2[mt][3],
                         vb4[nt >> 1][(nt & 1) * 2], vb4[nt >> 1][(nt & 1) * 2 + 1]);
    }

#pragma unroll
    for (int mt = 0; mt < 2; mt++)
#pragma unroll
        for (int h8 = 0; h8 < 2; h8++) {
            int p = mh * 32 + mt * 16 + g + h8 * 8;
            if (p < 49) {
                int r = p / 7, c = p - r * 7;
                int hh = wi * 7 + r + shift; if (hh >= 56) hh -= 56;
                int ww = wj * 7 + c + shift; if (ww >= 56) ww -= 56;
                size_t gt = (size_t)bimg * 3136 + hh * 56 + ww;
                __half* op = o + gt * 384 + head * 32;
#pragma unroll
                for (int nt = 0; nt < 4; nt++)
                    *(__half2*)&op[nt * 8 + 2 * t] =
                        __floats2half2_rn(o2[mt][nt][h8 * 2], o2[mt][nt][h8 * 2 + 1]);
            }
        }
}

// ---------------- launcher --------------------------------------------------
extern "C" void kernel_launch(void* const* d_in, const int* in_sizes, int n_in,
                              void* d_out, int out_size)
{
    const float* x     = (const float*)d_in[0];
    const float* n1g   = (const float*)d_in[1];
    const float* n1b   = (const float*)d_in[2];
    const float* qkvw  = (const float*)d_in[3];
    const float* qkvb  = (const float*)d_in[4];
    const float* rpb   = (const float*)d_in[5];
    const float* projw = (const float*)d_in[6];
    const float* projb = (const float*)d_in[7];
    const float* n2g   = (const float*)d_in[8];
    const float* n2b   = (const float*)d_in[9];
    const float* fc1w  = (const float*)d_in[10];
    const float* fc1b  = (const float*)d_in[11];
    const float* fc2w  = (const float*)d_in[12];
    const float* fc2b  = (const float*)d_in[13];
    float* out = (float*)d_out;

    __half *p_xn, *p_qkv, *p_o, *p_h1, *p_wt;
    cudaGetSymbolAddress((void**)&p_xn,  g_xn);
    cudaGetSymbolAddress((void**)&p_qkv, g_qkv);
    cudaGetSymbolAddress((void**)&p_o,   g_o);
    cudaGetSymbolAddress((void**)&p_h1,  g_h1);
    cudaGetSymbolAddress((void**)&p_wt,  g_wt);

    cudaFuncSetAttribute((void*)gemm_fp16<0, __half>, cudaFuncAttributeMaxDynamicSharedMemorySize, GEMM_SMEM);
    cudaFuncSetAttribute((void*)gemm_fp16<1, __half>, cudaFuncAttributeMaxDynamicSharedMemorySize, GEMM_SMEM);
    cudaFuncSetAttribute((void*)gemm_fp16<2, float>,  cudaFuncAttributeMaxDynamicSharedMemorySize, GEMM_SMEM);
    cudaFuncSetAttribute((void*)attn_mma, cudaFuncAttributeMaxDynamicSharedMemorySize, ATT_SMEM);

    transpose_all<<<1728, 256>>>(qkvw, projw, fc1w, fc2w, p_wt, 0);
    transpose_all<<<1728, 256>>>(qkvw, projw, fc1w, fc2w, p_wt, 1);

    for (int i = 0; i < 2; i++) {
        int shift = i ? 3 : 0;
        size_t base = (size_t)i * 1769472;
        if (i == 0)
            ln_warp<1><<<TOK / 8, 256>>>(x, n1g, n1b, p_xn, out);
        else
            ln_warp<0><<<TOK / 8, 256>>>(out, n1g + 384, n1b + 384, p_xn, nullptr);
        gemm_fp16<0, __half><<<dim3(9, 392), 512, GEMM_SMEM>>>(
            p_xn, p_wt + base, qkvb + i * 1152, p_qkv, 1152, 384);
        attn_mma<<<3072, 256, ATT_SMEM>>>(p_qkv, rpb + i * 169 * 12, p_o, shift);
        gemm_fp16<2, float><<<dim3(3, 392), 512, GEMM_SMEM>>>(
            p_o, p_wt + base + 442368, projb + i * 384, out, 384, 384);
        ln_warp<0><<<TOK / 8, 256>>>(out, n2g + i * 384, n2b + i * 384, p_xn, nullptr);
        gemm_fp16<1, __half><<<dim3(12, 392), 512, GEMM_SMEM>>>(
            p_xn, p_wt + base + 589824, fc1b + i * 1536, p_h1, 1536, 384);
        gemm_fp16<2, float><<<dim3(3, 392), 512, GEMM_SMEM>>>(
            p_h1, p_wt + base + 1179648, fc2b + i * 384, out, 384, 1536);
    }
}